// round 2
// baseline (speedup 1.0000x reference)
#include <cuda_runtime.h>
#include <cstdint>

// ============================================================================
// GroupFC: out[32768,1024] = data @ W^T + b (fp32)
// tcgen05 is unavailable (harness PTX target = sm_103 family, no 'a' suffix),
// so use classic mma.sync tf32 (legacy HMMA path) with RNA rounding in-loop.
// CTA tile 128x128, 4 warps (64x64 each), K chunk 32, 3-stage cp.async.
// ============================================================================

#define BATCH   32768
#define IN_DIM  1024
#define OUT_DIM 1024

#define BM 128
#define BN 128
#define KC 32
#define NCHUNK (IN_DIM / KC)          // 32
#define NST 3

#define S_ROW_B   144                 // 36 floats/row: banks (4g+t)%32 conflict-free, 16B aligned
#define STAGE_A   (BM * S_ROW_B)      // 18432 B
#define STAGE_BYTES (2 * STAGE_A)     // 36864 B (A tile then W tile)
#define SMEM_TOTAL  (NST * STAGE_BYTES) // 110592 B

// ---------------------------------------------------------------- helpers
__device__ __forceinline__ uint32_t smem_u32(const void* p) {
    uint32_t a;
    asm("{ .reg .u64 t; cvta.to.shared.u64 t, %1; cvt.u32.u64 %0, t; }"
        : "=r"(a) : "l"(p));
    return a;
}

__device__ __forceinline__ void cp16(uint32_t dst, const void* src) {
    asm volatile("cp.async.cg.shared.global [%0], [%1], 16;"
                 :: "r"(dst), "l"(src));
}
#define CP_COMMIT() asm volatile("cp.async.commit_group;" ::: "memory")
#define CP_WAIT_1() asm volatile("cp.async.wait_group 1;" ::: "memory")

// unbiased fp32 -> tf32 (round to nearest, ties away)
__device__ __forceinline__ uint32_t f2t(float x) {
    uint32_t r;
    asm("cvt.rna.tf32.f32 %0, %1;" : "=r"(r) : "f"(x));
    return r;
}

__device__ __forceinline__ void mma8(float* c,
                                     uint32_t a0, uint32_t a1, uint32_t a2, uint32_t a3,
                                     uint32_t b0, uint32_t b1) {
    asm volatile(
        "mma.sync.aligned.m16n8k8.row.col.f32.tf32.tf32.f32 "
        "{%0,%1,%2,%3}, {%4,%5,%6,%7}, {%8,%9}, {%0,%1,%2,%3};"
        : "+f"(c[0]), "+f"(c[1]), "+f"(c[2]), "+f"(c[3])
        : "r"(a0), "r"(a1), "r"(a2), "r"(a3), "r"(b0), "r"(b1));
}

// ---------------------------------------------------------------- kernel
// grid = (32768/128) * (1024/128) = 256 * 8 = 2048 CTAs, 128 threads.
// bid: nt = bid & 7 (inner) so 8 consecutive CTAs share one A stripe in L2;
// W (4MB) stays L2-resident.
extern "C" __global__ void __launch_bounds__(128, 2)
groupfc_tf32_kernel(const float* __restrict__ A, const float* __restrict__ W,
                    const float* __restrict__ bias, float* __restrict__ out) {
    extern __shared__ char smem[];
    const uint32_t sb = smem_u32(smem);

    const int tid  = threadIdx.x;
    const int wid  = tid >> 5;
    const int lane = tid & 31;
    const int g    = lane >> 2;     // group id (rows / cols within frag)
    const int t    = lane & 3;      // thread-in-group (k / paired cols)
    const int wm   = wid >> 1;      // warp row (0..1)
    const int wn   = wid & 1;       // warp col (0..1)

    const int mt = blockIdx.x >> 3;
    const int nt = blockIdx.x & 7;
    const int m0 = mt * BM;
    const int n0 = nt * BN;

    // staging assignment: thread fills k4 = tid&7 (16B column), rows erow+16i
    const int erow = tid >> 3;
    const int ek4  = tid & 7;
    const float* gA = A + (size_t)(m0 + erow) * IN_DIM + ek4 * 4;
    const float* gW = W + (size_t)(n0 + erow) * IN_DIM + ek4 * 4;
    const uint32_t sdst = sb + (uint32_t)erow * S_ROW_B + (uint32_t)ek4 * 16;

    float c[4][8][4];
#pragma unroll
    for (int mi = 0; mi < 4; mi++)
#pragma unroll
        for (int ni = 0; ni < 8; ni++)
#pragma unroll
            for (int j = 0; j < 4; j++) c[mi][ni][j] = 0.0f;

    // ---- stage fill: 16 cp.async (8 for A, 8 for W) per thread
#define FILL(cc, s)                                                          \
    do {                                                                     \
        const uint32_t _sa = sdst + (uint32_t)(s) * STAGE_BYTES;             \
        const uint32_t _sw = _sa + STAGE_A;                                  \
        const float* _pa = gA + (size_t)(cc) * KC;                          \
        const float* _pw = gW + (size_t)(cc) * KC;                          \
        _Pragma("unroll")                                                    \
        for (int _i = 0; _i < 8; _i++) {                                     \
            cp16(_sa + _i * 16 * S_ROW_B, _pa + (size_t)_i * 16 * IN_DIM);   \
            cp16(_sw + _i * 16 * S_ROW_B, _pw + (size_t)_i * 16 * IN_DIM);   \
        }                                                                    \
    } while (0)

    FILL(0, 0); CP_COMMIT();
    FILL(1, 1); CP_COMMIT();

    const int arow0 = wm * 64 + g;   // A smem row base for this lane
    const int brow0 = wn * 64 + g;   // W smem row base for this lane

#pragma unroll 1
    for (int cc = 0; cc < NCHUNK; cc++) {
        CP_WAIT_1();
        __syncthreads();

        const int s = cc % NST;
        const char* ps = smem + (size_t)s * STAGE_BYTES;
        const char* pb = ps + STAGE_A;

#pragma unroll
        for (int ks = 0; ks < 4; ks++) {
            const int kb = ks * 8 + t;

            uint32_t a[4][4];
#pragma unroll
            for (int mi = 0; mi < 4; mi++) {
                const char* base = ps + (size_t)(arow0 + mi * 16) * S_ROW_B + (size_t)kb * 4;
                a[mi][0] = f2t(*(const float*)(base));
                a[mi][1] = f2t(*(const float*)(base + 8 * S_ROW_B));
                a[mi][2] = f2t(*(const float*)(base + 16));
                a[mi][3] = f2t(*(const float*)(base + 8 * S_ROW_B + 16));
            }
            uint32_t b[8][2];
#pragma unroll
            for (int ni = 0; ni < 8; ni++) {
                const char* base = pb + (size_t)(brow0 + ni * 8) * S_ROW_B + (size_t)kb * 4;
                b[ni][0] = f2t(*(const float*)(base));
                b[ni][1] = f2t(*(const float*)(base + 16));
            }
#pragma unroll
            for (int mi = 0; mi < 4; mi++)
#pragma unroll
                for (int ni = 0; ni < 8; ni++)
                    mma8(c[mi][ni], a[mi][0], a[mi][1], a[mi][2], a[mi][3],
                         b[ni][0], b[ni][1]);
        }

        if (cc + 2 < NCHUNK) { FILL(cc + 2, (cc + 2) % NST); }
        CP_COMMIT();
    }

    // ---- epilogue: bias add + vectorized store
#pragma unroll
    for (int mi = 0; mi < 4; mi++) {
        const int r = m0 + wm * 64 + mi * 16 + g;
        float* o0 = out + (size_t)r * OUT_DIM + n0 + wn * 64 + 2 * t;
        float* o1 = o0 + 8 * OUT_DIM;
#pragma unroll
        for (int ni = 0; ni < 8; ni++) {
            const int col = n0 + wn * 64 + ni * 8 + 2 * t;
            const float b0v = __ldg(bias + col);
            const float b1v = __ldg(bias + col + 1);
            float2 v0 = make_float2(c[mi][ni][0] + b0v, c[mi][ni][1] + b1v);
            float2 v1 = make_float2(c[mi][ni][2] + b0v, c[mi][ni][3] + b1v);
            *(float2*)(o0 + ni * 8) = v0;
            *(float2*)(o1 + ni * 8) = v1;
        }
    }
}

// ---------------------------------------------------------------- launch
extern "C" void kernel_launch(void* const* d_in, const int* in_sizes, int n_in,
                              void* d_out, int out_size) {
    const float* A    = (const float*)d_in[0];   // data [32768,1024]
    const float* W    = (const float*)d_in[1];   // W    [1024,1024]
    const float* bias = (const float*)d_in[2];   // b    [1024]
    float* out = (float*)d_out;
    (void)in_sizes; (void)n_in; (void)out_size;

    cudaFuncSetAttribute(groupfc_tf32_kernel,
                         cudaFuncAttributeMaxDynamicSharedMemorySize, SMEM_TOTAL);

    const int grid = (BATCH / BM) * (OUT_DIM / BN);  // 2048
    groupfc_tf32_kernel<<<grid, 128, SMEM_TOTAL>>>(A, W, bias, out);
}

// round 3
// speedup vs baseline: 1.2515x; 1.2515x over previous
#include <cuda_runtime.h>
#include <cstdint>

// ============================================================================
// GroupFC: out[32768,1024] = data @ W^T + b (fp32), mma.sync tf32 (sm_103 ok).
// R3: W pre-rounded (RNA) + k-pair permuted -> B frags via single LDS.64,
//     SW128 chunk swizzle (no padding) -> conflict-free, 32KB/stage.
//     A rounded in-loop (cvt.rna). CTA 128x128, 4 warps 64x64, 3-stage cp.async.
// ============================================================================

#define BATCH   32768
#define IN_DIM  1024
#define OUT_DIM 1024

#define BM 128
#define BN 128
#define KC 32
#define NCHUNK (IN_DIM / KC)            // 32
#define NST 3

#define TILE_BYTES  16384               // 128 rows x 128 B
#define STAGE_BYTES (2 * TILE_BYTES)    // A tile + B tile
#define SMEM_TOTAL  (NST * STAGE_BYTES) // 98304 B -> 2 CTAs/SM

// W, RNA-rounded, k-permuted within each 8-group: [k0,k4,k1,k5,k2,k6,k3,k7]
__device__ float g_W[(size_t)OUT_DIM * IN_DIM];   // 4 MB static scratch

// ---------------------------------------------------------------- helpers
__device__ __forceinline__ void cp16(uint32_t dst, const void* src) {
    asm volatile("cp.async.cg.shared.global [%0], [%1], 16;"
                 :: "r"(dst), "l"(src));
}
#define CP_COMMIT() asm volatile("cp.async.commit_group;" ::: "memory")
#define CP_WAIT_1() asm volatile("cp.async.wait_group 1;" ::: "memory")

__device__ __forceinline__ uint32_t smem_u32(const void* p) {
    uint32_t a;
    asm("{ .reg .u64 t; cvta.to.shared.u64 t, %1; cvt.u32.u64 %0, t; }"
        : "=r"(a) : "l"(p));
    return a;
}

// unbiased fp32 -> tf32 (round-to-nearest-away)
__device__ __forceinline__ uint32_t f2t(float x) {
    uint32_t r;
    asm("cvt.rna.tf32.f32 %0, %1;" : "=r"(r) : "f"(x));
    return r;
}
__device__ __forceinline__ float f2tf(float x) {
    uint32_t r = f2t(x);
    return __uint_as_float(r);
}

__device__ __forceinline__ void mma8(float* c,
                                     uint32_t a0, uint32_t a1, uint32_t a2, uint32_t a3,
                                     uint32_t b0, uint32_t b1) {
    asm volatile(
        "mma.sync.aligned.m16n8k8.row.col.f32.tf32.tf32.f32 "
        "{%0,%1,%2,%3}, {%4,%5,%6,%7}, {%8,%9}, {%0,%1,%2,%3};"
        : "+f"(c[0]), "+f"(c[1]), "+f"(c[2]), "+f"(c[3])
        : "r"(a0), "r"(a1), "r"(a2), "r"(a3), "r"(b0), "r"(b1));
}

// ---------------------------------------------------------------- W prep
// 1024*1024 floats = 131072 groups of 8. Round (RNA) + permute k within group.
__global__ void __launch_bounds__(256) prep_W_kernel(const float4* __restrict__ src) {
    const int gidx = blockIdx.x * blockDim.x + threadIdx.x;   // group index
    float4 lo = src[gidx * 2];       // k0..k3
    float4 hi = src[gidx * 2 + 1];   // k4..k7
    float4 c0, c1;
    c0.x = f2tf(lo.x); c0.y = f2tf(hi.x); c0.z = f2tf(lo.y); c0.w = f2tf(hi.y);
    c1.x = f2tf(lo.z); c1.y = f2tf(hi.z); c1.z = f2tf(lo.w); c1.w = f2tf(hi.w);
    float4* dst = reinterpret_cast<float4*>(g_W);
    dst[gidx * 2]     = c0;
    dst[gidx * 2 + 1] = c1;
}

// ---------------------------------------------------------------- GEMM
// grid = 256 * 8 = 2048 CTAs, 128 threads. nt inner: 8 CTAs share an A stripe.
extern "C" __global__ void __launch_bounds__(128, 2)
groupfc_tf32_kernel(const float* __restrict__ A, const float* __restrict__ bias,
                    float* __restrict__ out) {
    extern __shared__ char smem[];
    const uint32_t sb = smem_u32(smem);

    const int tid  = threadIdx.x;
    const int wid  = tid >> 5;
    const int lane = tid & 31;
    const int g    = lane >> 2;
    const int t    = lane & 3;
    const int wm   = wid >> 1;
    const int wn   = wid & 1;

    const int mt = blockIdx.x >> 3;
    const int nt = blockIdx.x & 7;
    const int m0 = mt * BM;
    const int n0 = nt * BN;

    // staging: thread fills chunk ech (16B) of rows erow+16i; swizzled chunk
    // is constant per thread: ech ^ (erow & 7).
    const int erow = tid >> 3;
    const int ech  = tid & 7;
    const int sch  = (ech ^ (erow & 7));
    const float* gA = A + (size_t)(m0 + erow) * IN_DIM + ech * 4;
    const float* gW = g_W + (size_t)(n0 + erow) * IN_DIM + ech * 4;
    const uint32_t sdA = sb + (uint32_t)erow * 128 + (uint32_t)sch * 16;
    const uint32_t sdB = sdA + TILE_BYTES;

    float c[4][8][4];
#pragma unroll
    for (int mi = 0; mi < 4; mi++)
#pragma unroll
        for (int ni = 0; ni < 8; ni++)
#pragma unroll
            for (int j = 0; j < 4; j++) c[mi][ni][j] = 0.0f;

#define FILL(cc, s)                                                           \
    do {                                                                      \
        const uint32_t _o = (uint32_t)(s) * STAGE_BYTES;                      \
        const float* _pa = gA + (size_t)(cc) * KC;                            \
        const float* _pw = gW + (size_t)(cc) * KC;                            \
        _Pragma("unroll")                                                     \
        for (int _i = 0; _i < 8; _i++) {                                      \
            cp16(sdA + _o + _i * 16 * 128, _pa + (size_t)_i * 16 * IN_DIM);   \
            cp16(sdB + _o + _i * 16 * 128, _pw + (size_t)_i * 16 * IN_DIM);   \
        }                                                                     \
    } while (0)

    FILL(0, 0); CP_COMMIT();
    FILL(1, 1); CP_COMMIT();

    const int arow0 = wm * 64 + g;      // (row & 7) == g for all mi offsets
    const int brow0 = wn * 64 + g;

#pragma unroll 1
    for (int cc = 0; cc < NCHUNK; cc++) {
        CP_WAIT_1();
        __syncthreads();

        const int s = cc % NST;
        const char* pa = smem + (size_t)s * STAGE_BYTES;
        const char* pb = pa + TILE_BYTES;

#pragma unroll
        for (int ks = 0; ks < 4; ks++) {
            // A fragments: LDS.32 at swizzled chunks (2ks^g) and ((2ks+1)^g)
            const int ca0 = ((2 * ks) ^ g) * 16 + t * 4;
            const int ca1 = ((2 * ks + 1) ^ g) * 16 + t * 4;
            uint32_t a[4][4];
#pragma unroll
            for (int mi = 0; mi < 4; mi++) {
                const char* b0 = pa + (size_t)(arow0 + mi * 16) * 128;
                const char* b1 = b0 + 8 * 128;
                a[mi][0] = f2t(*(const float*)(b0 + ca0));
                a[mi][1] = f2t(*(const float*)(b1 + ca0));
                a[mi][2] = f2t(*(const float*)(b0 + ca1));
                a[mi][3] = f2t(*(const float*)(b1 + ca1));
            }
            // B fragments: one LDS.64 per ni (pre-rounded, k-pair adjacent)
            const int cb = ((2 * ks + (t >> 1)) ^ g) * 16 + (t & 1) * 8;
            uint2 b[8];
#pragma unroll
            for (int ni = 0; ni < 8; ni++)
                b[ni] = *(const uint2*)(pb + (size_t)(brow0 + ni * 8) * 128 + cb);

#pragma unroll
            for (int mi = 0; mi < 4; mi++)
#pragma unroll
                for (int ni = 0; ni < 8; ni++)
                    mma8(c[mi][ni], a[mi][0], a[mi][1], a[mi][2], a[mi][3],
                         b[ni].x, b[ni].y);
        }

        if (cc + 2 < NCHUNK) { FILL(cc + 2, (cc + 2) % NST); }
        CP_COMMIT();
    }

    // ---- epilogue: bias add + float2 stores
#pragma unroll
    for (int mi = 0; mi < 4; mi++) {
        const int r = m0 + wm * 64 + mi * 16 + g;
        float* o0 = out + (size_t)r * OUT_DIM + n0 + wn * 64 + 2 * t;
        float* o1 = o0 + 8 * OUT_DIM;
#pragma unroll
        for (int ni = 0; ni < 8; ni++) {
            const int col = n0 + wn * 64 + ni * 8 + 2 * t;
            const float b0v = __ldg(bias + col);
            const float b1v = __ldg(bias + col + 1);
            *(float2*)(o0 + ni * 8) = make_float2(c[mi][ni][0] + b0v, c[mi][ni][1] + b1v);
            *(float2*)(o1 + ni * 8) = make_float2(c[mi][ni][2] + b0v, c[mi][ni][3] + b1v);
        }
    }
}

// ---------------------------------------------------------------- launch
extern "C" void kernel_launch(void* const* d_in, const int* in_sizes, int n_in,
                              void* d_out, int out_size) {
    const float* A    = (const float*)d_in[0];
    const float* W    = (const float*)d_in[1];
    const float* bias = (const float*)d_in[2];
    float* out = (float*)d_out;
    (void)in_sizes; (void)n_in; (void)out_size;

    cudaFuncSetAttribute(groupfc_tf32_kernel,
                         cudaFuncAttributeMaxDynamicSharedMemorySize, SMEM_TOTAL);

    prep_W_kernel<<<512, 256>>>(reinterpret_cast<const float4*>(W));

    const int grid = (BATCH / BM) * (OUT_DIM / BN);  // 2048
    groupfc_tf32_kernel<<<grid, 128, SMEM_TOTAL>>>(A, bias, out);
}